// round 1
// baseline (speedup 1.0000x reference)
#include <cuda_runtime.h>
#include <cstdint>

typedef unsigned long long ull;

// ---------- packed f32x2 helpers (FFMA2 path, sm_103a) ----------
__device__ __forceinline__ ull f2pack(float lo, float hi) {
    ull r; asm("mov.b64 %0,{%1,%2};" : "=l"(r) : "f"(lo), "f"(hi)); return r;
}
__device__ __forceinline__ void f2unpack(ull a, float& lo, float& hi) {
    asm("mov.b64 {%0,%1},%2;" : "=f"(lo), "=f"(hi) : "l"(a));
}
__device__ __forceinline__ ull f2mul(ull a, ull b) {
    ull r; asm("mul.rn.f32x2 %0,%1,%2;" : "=l"(r) : "l"(a), "l"(b)); return r;
}
__device__ __forceinline__ ull f2add(ull a, ull b) {
    ull r; asm("add.rn.f32x2 %0,%1,%2;" : "=l"(r) : "l"(a), "l"(b)); return r;
}
__device__ __forceinline__ ull f2fma(ull a, ull b, ull c) {
    ull r; asm("fma.rn.f32x2 %0,%1,%2,%3;" : "=l"(r) : "l"(a), "l"(b), "l"(c)); return r;
}

#define TILE   32
#define HALO   5
#define IN_DIM 42          // TILE + 2*HALO
#define NPIX   12582912.0  // 48 * 512 * 512

__device__ double g_acc;

__global__ void ssim_zero_k() { g_acc = 0.0; }

__global__ void ssim_final_k(float* out) {
    out[0] = 1.0f - (float)(g_acc * (1.0 / NPIX));
}

// smem (dynamic, in ull units):
//  sp[42*42]          packed pred pair tile (halo)
//  st[42*42]          packed target pair tile
//  hb[5][42][32]      horizontally blurred signals (mu1,mu2,pp,tt,pt)
// total = (1764*2 + 6720) * 8 = 81984 bytes
__global__ __launch_bounds__(256) void ssim_main_k(
    const float* __restrict__ pred,
    const float* __restrict__ targ,
    const float* __restrict__ win)
{
    extern __shared__ ull sm[];
    ull* sp = sm;
    ull* st = sm + 1764;
    ull* hb = sm + 3528;

    const int tid = threadIdx.x;

    // --- recover separable 1D window from the 2D outer-product window ---
    // win[5][j] = w1[5]*w1[j], sum_j win[5][j] = w1[5]  =>  w1[j] = win[55+j]/rowsum
    float rowsum = 0.f;
#pragma unroll
    for (int j = 0; j < 11; j++) rowsum += __ldg(win + 55 + j);
    const float invr = 1.0f / rowsum;
    ull ww[11];
#pragma unroll
    for (int j = 0; j < 11; j++) {
        float w = __ldg(win + 55 + j) * invr;
        ww[j] = f2pack(w, w);
    }

    const int ox = blockIdx.x * TILE;
    const int oy = blockIdx.y * TILE;
    const int pz = blockIdx.z;                  // plane pair 0..23
    const float* p0 = pred + (size_t)pz * 524288;
    const float* p1 = p0 + 262144;
    const float* t0 = targ + (size_t)pz * 524288;
    const float* t1 = t0 + 262144;

    // --- load 42x42 halo tiles (zero pad outside image) ---
#pragma unroll
    for (int i = 0; i < 7; i++) {
        int idx = tid + i * 256;
        if (idx < 1764) {
            int r = idx / IN_DIM, c = idx - r * IN_DIM;
            int gy = oy + r - HALO, gx = ox + c - HALO;
            bool inb = ((unsigned)gy < 512u) && ((unsigned)gx < 512u);
            float a0 = 0.f, a1 = 0.f, b0 = 0.f, b1 = 0.f;
            if (inb) {
                int g = gy * 512 + gx;
                a0 = __ldg(p0 + g); a1 = __ldg(p1 + g);
                b0 = __ldg(t0 + g); b1 = __ldg(t1 + g);
            }
            sp[idx] = f2pack(a0, a1);
            st[idx] = f2pack(b0, b1);
        }
    }
    __syncthreads();

    // --- horizontal blur: 42 rows x 8 x-groups (4 outputs each) = 336 items ---
    for (int it = tid; it < 336; it += 256) {
        const int r = it >> 3;
        const int x0 = (it & 7) * 4;
        ull acc[5][4];
#pragma unroll
        for (int s = 0; s < 5; s++)
#pragma unroll
            for (int j = 0; j < 4; j++) acc[s][j] = 0ULL;

        const ull* rp = sp + r * IN_DIM + x0;
        const ull* rt = st + r * IN_DIM + x0;
#pragma unroll
        for (int k = 0; k < 14; k++) {
            ull p = rp[k], t = rt[k];
            ull pp = f2mul(p, p), tt = f2mul(t, t), pt = f2mul(p, t);
#pragma unroll
            for (int j = 0; j < 4; j++) {
                const int ki = k - j;
                if (ki >= 0 && ki <= 10) {
                    ull w = ww[ki];
                    acc[0][j] = f2fma(p,  w, acc[0][j]);
                    acc[1][j] = f2fma(t,  w, acc[1][j]);
                    acc[2][j] = f2fma(pp, w, acc[2][j]);
                    acc[3][j] = f2fma(tt, w, acc[3][j]);
                    acc[4][j] = f2fma(pt, w, acc[4][j]);
                }
            }
        }
#pragma unroll
        for (int s = 0; s < 5; s++)
#pragma unroll
            for (int j = 0; j < 4; j++)
                hb[s * 1344 + r * 32 + x0 + j] = acc[s][j];
    }
    __syncthreads();

    // --- vertical blur + SSIM epilogue: each thread does column x, rows y0..y0+3 ---
    float lsum = 0.f;
    {
        const int x  = tid & 31;
        const int y0 = (tid >> 5) * 4;
        ull acc[5][4];
#pragma unroll
        for (int s = 0; s < 5; s++)
#pragma unroll
            for (int j = 0; j < 4; j++) acc[s][j] = 0ULL;

#pragma unroll
        for (int k = 0; k < 14; k++) {
            const int row = y0 + k;
            ull v0 = hb[0 * 1344 + row * 32 + x];
            ull v1 = hb[1 * 1344 + row * 32 + x];
            ull v2 = hb[2 * 1344 + row * 32 + x];
            ull v3 = hb[3 * 1344 + row * 32 + x];
            ull v4 = hb[4 * 1344 + row * 32 + x];
#pragma unroll
            for (int j = 0; j < 4; j++) {
                const int ki = k - j;
                if (ki >= 0 && ki <= 10) {
                    ull w = ww[ki];
                    acc[0][j] = f2fma(v0, w, acc[0][j]);
                    acc[1][j] = f2fma(v1, w, acc[1][j]);
                    acc[2][j] = f2fma(v2, w, acc[2][j]);
                    acc[3][j] = f2fma(v3, w, acc[3][j]);
                    acc[4][j] = f2fma(v4, w, acc[4][j]);
                }
            }
        }

        const ull TWO  = f2pack(2.0f, 2.0f);
        const ull C1p  = f2pack(1e-4f, 1e-4f);
        const ull C2p  = f2pack(9e-4f, 9e-4f);
        const ull EPSp = f2pack(1e-8f, 1e-8f);
        const ull SGN  = 0x8000000080000000ULL;

#pragma unroll
        for (int j = 0; j < 4; j++) {
            ull mu1 = acc[0][j], mu2 = acc[1][j];
            ull bpp = acc[2][j], btt = acc[3][j], bpt = acc[4][j];
            ull nmu1 = mu1 ^ SGN;
            ull nmu2 = mu2 ^ SGN;
            ull mu1mu2 = f2mul(mu1, mu2);
            ull mu1sq  = f2mul(mu1, mu1);
            ull mu2sq  = f2mul(mu2, mu2);
            ull sig1   = f2fma(nmu1, mu1, bpp);   // blur(pp) - mu1^2
            ull sig2   = f2fma(nmu2, mu2, btt);
            ull sig12  = f2fma(nmu1, mu2, bpt);
            ull num1 = f2fma(mu1mu2, TWO, C1p);   // 2*mu1mu2 + C1
            ull num2 = f2fma(sig12,  TWO, C2p);   // 2*sig12 + C2
            ull den1 = f2add(f2add(mu1sq, mu2sq), C1p);
            ull den2 = f2add(f2add(sig1, sig2), C2p);
            ull num  = f2mul(num1, num2);
            ull den  = f2fma(den1, den2, EPSp);
            float n0, n1, d0, d1;
            f2unpack(num, n0, n1);
            f2unpack(den, d0, d1);
            lsum += __fdividef(n0, d0) + __fdividef(n1, d1);
        }
    }

    // --- block reduction -> double atomic ---
#pragma unroll
    for (int o = 16; o; o >>= 1) lsum += __shfl_xor_sync(0xffffffffu, lsum, o);
    __shared__ float warp_part[8];
    if ((tid & 31) == 0) warp_part[tid >> 5] = lsum;
    __syncthreads();
    if (tid < 32) {
        float v = (tid < 8) ? warp_part[tid] : 0.f;
#pragma unroll
        for (int o = 4; o; o >>= 1) v += __shfl_xor_sync(0xffffffffu, v, o);
        if (tid == 0) atomicAdd(&g_acc, (double)v);
    }
}

extern "C" void kernel_launch(void* const* d_in, const int* in_sizes, int n_in,
                              void* d_out, int out_size)
{
    const float* pred = (const float*)d_in[0];
    const float* targ = (const float*)d_in[1];
    const float* win  = (const float*)d_in[2];
    float* out = (float*)d_out;

    const int smem_bytes = 81984;
    cudaFuncSetAttribute(ssim_main_k, cudaFuncAttributeMaxDynamicSharedMemorySize, smem_bytes);

    ssim_zero_k<<<1, 1>>>();
    dim3 grid(16, 16, 24), blk(256);
    ssim_main_k<<<grid, blk, smem_bytes>>>(pred, targ, win);
    ssim_final_k<<<1, 1>>>(out);
}